// round 17
// baseline (speedup 1.0000x reference)
#include <cuda_runtime.h>
#include <cuda_fp16.h>
#include <stdint.h>
#include <math.h>

#define EMBED 512
#define NBATCH 8
#define QLEN 2048
#define KLEN 4096
#define MQ (NBATCH*QLEN)
#define MK (NBATCH*KLEN)
#define NBLK (KLEN/128)
#define NW (EMBED*EMBED)
#define NXE (MQ*EMBED)

__device__ __half g_x16[MQ*EMBED];
__device__ __half g_y16[MK*EMBED];
__device__ __half g_yT16[(size_t)NBATCH*EMBED*KLEN];
__device__ __half g_W16[4][NW];            // 0 Wq->WqkT, 1 Wk, 2 Wv->Wvo, 3 Wo
__device__ __half g_T1[NW], g_T2[NW], g_T3[NW];
__device__ __half g_Q16[MQ*EMBED];         // Q', later reused as Z
__device__ __half g_E16[(size_t)MQ*KLEN];
__device__ float  g_Esum[(size_t)MQ*NBLK];
__device__ int    g_cnt[512];  // [0]=A cvtXW, [1]=B cvtY, [2]=C trW3, [3]=D gemmW2,
                               // [8,136) qcnt, [136,264) ecnt, [264,392) zcnt

__device__ __forceinline__ uint32_t smem_u32(const void* p){
    uint32_t a;
    asm("{ .reg .u64 t; cvta.to.shared.u64 t, %1; cvt.u32.u64 %0, t; }" : "=r"(a) : "l"(p));
    return a;
}
#define CP16(s,g)   asm volatile("cp.async.cg.shared.global [%0], [%1], 16;" :: "r"(s), "l"(g) : "memory")
#define CP_COMMIT() asm volatile("cp.async.commit_group;" ::: "memory")
#define CP_WAIT1()  asm volatile("cp.async.wait_group 1;" ::: "memory")
#define CP_WAIT0()  asm volatile("cp.async.wait_group 0;" ::: "memory")

__device__ __forceinline__ void ldm4(uint32_t* r, uint32_t a){
    asm volatile("ldmatrix.sync.aligned.m8n8.x4.shared.b16 {%0,%1,%2,%3}, [%4];"
        : "=r"(r[0]), "=r"(r[1]), "=r"(r[2]), "=r"(r[3]) : "r"(a));
}
__device__ __forceinline__ void mma_f16(float* c, const uint32_t* a, const uint32_t* b){
    asm volatile("mma.sync.aligned.m16n8k16.row.col.f32.f16.f16.f32 "
        "{%0,%1,%2,%3}, {%4,%5,%6,%7}, {%8,%9}, {%0,%1,%2,%3};"
        : "+f"(c[0]), "+f"(c[1]), "+f"(c[2]), "+f"(c[3])
        : "r"(a[0]), "r"(a[1]), "r"(a[2]), "r"(a[3]), "r"(b[0]), "r"(b[1]));
}

// ---------------- shared GEMM core (frozen R10/R13 config) ----------------
#define STAGE_B 32768
#define GSMEM   (3*STAGE_B + 1024)

template<int EPI>
__device__ __forceinline__ void gemm_core(
    const __half* __restrict__ A, int lda,
    const __half* __restrict__ B, int ldb, int Kdim,
    int m0, int n0,
    __half* __restrict__ C16, int ldc,
    float* __restrict__ Cf, const float* __restrict__ resid,
    const float* __restrict__ bias, float scale,
    float* __restrict__ esBase, int nblk, char* dynsm)
{
    const uint32_t smbase = smem_u32(dynsm);
    const uint32_t tiles = (smbase + 1023u) & ~1023u;
    const int tid = threadIdx.x, lane = tid & 31, wid = tid >> 5;
    const int wm = wid & 3, wn = wid >> 2;

    float acc[2][8][4];
    #pragma unroll
    for (int i = 0; i < 2; i++)
        #pragma unroll
        for (int j = 0; j < 8; j++)
            #pragma unroll
            for (int k = 0; k < 4; k++) acc[i][j][k] = 0.f;

    const int r_lane = (lane & 7) + ((lane >> 3) & 1) * 8;
    uint32_t aRow[2], aSw[2];
    #pragma unroll
    for (int mt = 0; mt < 2; mt++){
        int m_loc = wm * 32 + mt * 16 + r_lane;
        aRow[mt] = (uint32_t)(m_loc * 128);
        aSw[mt]  = (uint32_t)(m_loc & 7);
    }
    const uint32_t aCk = (lane >> 4) & 1;
    uint32_t bRow[4], bSw[4];
    {
        int n_base = wn * 64 + ((lane >> 4) & 1) * 8 + (lane & 7);
        #pragma unroll
        for (int g = 0; g < 4; g++){
            int n_loc = n_base + g * 16;
            bRow[g] = (uint32_t)(n_loc * 128);
            bSw[g]  = (uint32_t)(n_loc & 7);
        }
    }
    const uint32_t bCk = (lane >> 3) & 1;

    const int C = Kdim >> 6;

    auto load_stage = [&](int c){
        const uint32_t sb = tiles + (c % 3) * STAGE_B;
        const int k0 = c << 6;
        #pragma unroll
        for (int i = 0; i < 4; i++){
            int idx = tid + i * 256;
            int row = idx >> 3, ch = idx & 7;
            uint32_t so = (uint32_t)(row * 128 + ((ch ^ (row & 7)) << 4));
            CP16(sb + so, A + (size_t)(m0 + row) * lda + k0 + ch * 8);
        }
        #pragma unroll
        for (int i = 0; i < 4; i++){
            int idx = tid + i * 256;
            int row = idx >> 3, ch = idx & 7;
            uint32_t so = (uint32_t)(row * 128 + ((ch ^ (row & 7)) << 4));
            CP16(sb + 16384 + so, B + (size_t)(n0 + row) * ldb + k0 + ch * 8);
        }
    };

    load_stage(0); CP_COMMIT();
    load_stage(1); CP_COMMIT();

    for (int c = 0; c < C; c++){
        if (c < C - 1) CP_WAIT1(); else CP_WAIT0();
        __syncthreads();
        if (c + 2 < C){ load_stage(c + 2); CP_COMMIT(); }

        const uint32_t sb = tiles + (c % 3) * STAGE_B;
        #pragma unroll
        for (int ks = 0; ks < 4; ks++){
            uint32_t ah[2][4];
            #pragma unroll
            for (int mt = 0; mt < 2; mt++){
                uint32_t off = aRow[mt] + ((((uint32_t)(2 * ks) + aCk) ^ aSw[mt]) << 4);
                ldm4(ah[mt], sb + off);
            }
            uint32_t bb[8][2];
            #pragma unroll
            for (int g = 0; g < 4; g++){
                uint32_t off = bRow[g] + ((((uint32_t)(2 * ks) + bCk) ^ bSw[g]) << 4);
                uint32_t q[4];
                ldm4(q, sb + 16384 + off);
                bb[2*g][0]=q[0]; bb[2*g][1]=q[1]; bb[2*g+1][0]=q[2]; bb[2*g+1][1]=q[3];
            }
            #pragma unroll
            for (int mt = 0; mt < 2; mt++)
                #pragma unroll
                for (int nf = 0; nf < 8; nf++)
                    mma_f16(acc[mt][nf], ah[mt], bb[nf]);
        }
    }

    const int er = lane >> 2, ec = (lane & 3) * 2;
    if (EPI == 3){
        float* rs = reinterpret_cast<float*>(dynsm + (tiles - smbase));
        float rowp[2][2] = {};
        #pragma unroll
        for (int mt = 0; mt < 2; mt++)
            #pragma unroll
            for (int nf = 0; nf < 8; nf++){
                const int n = n0 + wn * 64 + nf * 8 + ec;
                #pragma unroll
                for (int rr = 0; rr < 2; rr++){
                    const int m = m0 + wm * 32 + mt * 16 + er + rr * 8;
                    float e0 = __expf(acc[mt][nf][rr*2]   * scale);
                    float e1 = __expf(acc[mt][nf][rr*2+1] * scale);
                    __half2 hp = __floats2half2_rn(e0, e1);
                    *reinterpret_cast<uint32_t*>(C16 + (size_t)m * ldc + n) = *reinterpret_cast<uint32_t*>(&hp);
                    rowp[mt][rr] += e0 + e1;
                }
            }
        __syncthreads();
        #pragma unroll
        for (int mt = 0; mt < 2; mt++)
            #pragma unroll
            for (int rr = 0; rr < 2; rr++){
                float v = rowp[mt][rr];
                v += __shfl_xor_sync(0xffffffffu, v, 1);
                v += __shfl_xor_sync(0xffffffffu, v, 2);
                if ((lane & 3) == 0){
                    int row = wm * 32 + mt * 16 + rr * 8 + er;
                    rs[wn * 128 + row] = v;
                }
            }
        __syncthreads();
        if (tid < 128)
            esBase[(size_t)(m0 + tid) * NBLK + nblk] = rs[tid] + rs[128 + tid];
        return;
    }
    if (EPI == 4){
        float invr[2][2];
        #pragma unroll
        for (int mt = 0; mt < 2; mt++)
            #pragma unroll
            for (int rr = 0; rr < 2; rr++){
                const int m = m0 + wm * 32 + mt * 16 + er + rr * 8;
                const float4* p = reinterpret_cast<const float4*>(esBase + (size_t)m * NBLK);
                float s = 0.f;
                #pragma unroll
                for (int i = 0; i < NBLK/4; i++){
                    float4 v = p[i];
                    s += (v.x + v.y) + (v.z + v.w);
                }
                invr[mt][rr] = 1.f / s;
            }
        #pragma unroll
        for (int mt = 0; mt < 2; mt++)
            #pragma unroll
            for (int nf = 0; nf < 8; nf++){
                const int n = n0 + wn * 64 + nf * 8 + ec;
                #pragma unroll
                for (int rr = 0; rr < 2; rr++){
                    const int m = m0 + wm * 32 + mt * 16 + er + rr * 8;
                    __half2 hp = __floats2half2_rn(acc[mt][nf][rr*2]   * invr[mt][rr],
                                                   acc[mt][nf][rr*2+1] * invr[mt][rr]);
                    *reinterpret_cast<uint32_t*>(C16 + (size_t)m * ldc + n) = *reinterpret_cast<uint32_t*>(&hp);
                }
            }
        return;
    }
    if (EPI == 2){
        #pragma unroll
        for (int mt = 0; mt < 2; mt++)
            #pragma unroll
            for (int nf = 0; nf < 8; nf++){
                const int n = n0 + wn * 64 + nf * 8 + ec;
                #pragma unroll
                for (int rr = 0; rr < 2; rr++){
                    const int m = m0 + wm * 32 + mt * 16 + er + rr * 8;
                    size_t off = (size_t)m * ldc + n;
                    float2 rv = *reinterpret_cast<const float2*>(resid + off);
                    float2 bv = *reinterpret_cast<const float2*>(bias + n);
                    float2 o;
                    o.x = acc[mt][nf][rr*2]   + rv.x + bv.x;
                    o.y = acc[mt][nf][rr*2+1] + rv.y + bv.y;
                    *reinterpret_cast<float2*>(Cf + off) = o;
                }
            }
        return;
    }
    // EPI 0
    #pragma unroll
    for (int mt = 0; mt < 2; mt++)
        #pragma unroll
        for (int nf = 0; nf < 8; nf++){
            const int n = n0 + wn * 64 + nf * 8 + ec;
            #pragma unroll
            for (int rr = 0; rr < 2; rr++){
                const int m = m0 + wm * 32 + mt * 16 + er + rr * 8;
                __half2 hp = __floats2half2_rn(acc[mt][nf][rr*2], acc[mt][nf][rr*2+1]);
                *reinterpret_cast<uint32_t*>(C16 + (size_t)m * ldc + n) = *reinterpret_cast<uint32_t*>(&hp);
            }
        }
}

// ---------------- dataflow helpers ----------------
__device__ __forceinline__ void gate(int idx, int target){
    if (threadIdx.x == 0){
        while (atomicAdd(&g_cnt[idx], 0) < target) __nanosleep(100);
    }
    __syncthreads();
}
__device__ __forceinline__ void signal(int idx){
    __syncthreads();
    if (threadIdx.x == 0){ __threadfence(); atomicAdd(&g_cnt[idx], 1); }
}

// ---------------- phase block counts ----------------
#define PA 1024                      // cvtXW
#define PC 768                       // trW3
#define PD 32                        // gemmW2
#define PB 2048                      // cvtY
#define PQ 512                       // qproj
#define PE 4096                      // gemmE
#define PZ 512                       // gemmZ
#define PO 512                       // gemmOut
#define OFF_C  (PA)
#define OFF_D  (OFF_C + PC)
#define OFF_B  (OFF_D + PD)
#define OFF_Q  (OFF_B + PB)
#define OFF_E  (OFF_Q + PQ)
#define OFF_Z  (OFF_E + PE)
#define OFF_O  (OFF_Z + PZ)
#define NTOT   (OFF_O + PO)          // 9504

// ---------------- megakernel: everything ----------------
__global__ void __launch_bounds__(256, 2)
mega(const float* __restrict__ x, const float* __restrict__ y,
     const float* __restrict__ Wq, const float* __restrict__ Wk,
     const float* __restrict__ Wv, const float* __restrict__ Wo,
     const float* __restrict__ bo, float* __restrict__ out, float scale)
{
    extern __shared__ char dynsm[];
    const int id = blockIdx.x;
    const int tid = threadIdx.x;

    if (id < PA){
        // ---- cvtXW: x + 4 weights -> fp16 (vec4, strided loop) ----
        const int NV4 = (NXE + 4*NW) / 4;              // 2359296
        for (int i = id * 256 + tid; i < NV4; i += PA * 256){
            int e = i * 4;
            const float* src; __half* dst;
            if (e < NXE){ src = x + e; dst = g_x16 + e; }
            else {
                int o = e - NXE;
                int w = o / NW, r = o % NW;
                src = (w == 0 ? Wq : w == 1 ? Wk : w == 2 ? Wv : Wo) + r;
                dst = &g_W16[0][0] + (size_t)w * NW + r;
            }
            float4 v = *reinterpret_cast<const float4*>(src);
            __half2 a = __floats2half2_rn(v.x, v.y);
            __half2 b = __floats2half2_rn(v.z, v.w);
            uint2 o2;
            o2.x = *reinterpret_cast<uint32_t*>(&a);
            o2.y = *reinterpret_cast<uint32_t*>(&b);
            *reinterpret_cast<uint2*>(dst) = o2;
        }
        signal(0);
    } else if (id < OFF_D){
        // ---- trW3: transpose Wq,Wk,Wv (fp16) ----
        gate(0, PA);
        __half (*s)[33] = reinterpret_cast<__half(*)[33]>(dynsm);
        const int r = id - OFF_C;
        const int z = r >> 8, rem = r & 255;
        const __half* src = &g_W16[z][0];
        __half* dst = (z == 0) ? g_T1 : (z == 1) ? g_T2 : g_T3;
        const int x0 = (rem & 15) * 32, y0 = (rem >> 4) * 32;
        const int tx = tid & 31, ty = tid >> 5;
        #pragma unroll
        for (int i = ty; i < 32; i += 8)
            s[i][tx] = src[(size_t)(y0 + i) * EMBED + x0 + tx];
        __syncthreads();
        #pragma unroll
        for (int i = ty; i < 32; i += 8)
            dst[(size_t)(x0 + i) * EMBED + y0 + tx] = s[tx][i];
        signal(2);
    } else if (id < OFF_B){
        // ---- gemmW2: WqkT = T2 @ T1^T-form ; Wvo = Wo @ T3^T-form ----
        gate(2, PC);
        const int r = id - OFF_D;
        const int z = r >> 4, rem = r & 15;
        const __half *A, *B; __half* D;
        if (z == 0){ A = g_T2; B = g_T1; D = &g_W16[0][0]; }
        else       { A = &g_W16[3][0]; B = g_T3; D = &g_W16[2][0]; }
        gemm_core<0>(A, EMBED, B, EMBED, EMBED,
                     (rem >> 2) * 128, (rem & 3) * 128,
                     D, EMBED, nullptr, nullptr, nullptr, 1.0f, nullptr, 0, dynsm);
        signal(3);
    } else if (id < OFF_Q){
        // ---- cvtY: y -> y16 + yT16 (8 tiles of 32x32 per block) ----
        __half (*s)[33] = reinterpret_cast<__half(*)[33]>(dynsm);
        const int r = id - OFF_B;
        for (int j = 0; j < 8; j++){
            const int t = r * 8 + j;                  // 0..16383
            const int b = t >> 11, rem = t & 2047;
            const int kk0 = (rem & 127) * 32, d0 = (rem >> 7) * 32;
            const int tx = tid & 31, ty = tid >> 5;
            const float* src = y + (size_t)b * KLEN * EMBED;
            __half* d1 = g_y16 + (size_t)b * KLEN * EMBED;
            __syncthreads();
            #pragma unroll
            for (int i = ty; i < 32; i += 8){
                __half h = __float2half(src[(size_t)(kk0 + i) * EMBED + d0 + tx]);
                d1[(size_t)(kk0 + i) * EMBED + d0 + tx] = h;
                s[i][tx] = h;
            }
            __syncthreads();
            __half* d2 = g_yT16 + (size_t)b * EMBED * KLEN;
            #pragma unroll
            for (int i = ty; i < 32; i += 8)
                d2[(size_t)(d0 + i) * KLEN + kk0 + tx] = s[tx][i];
        }
        signal(1);
    } else if (id < OFF_E){
        // ---- qproj: Q' = x16 @ WqkT^T ----
        const int r = id - OFF_Q;
        const int gm = r >> 2;
        gate(3, PD);
        gemm_core<0>(g_x16, EMBED, &g_W16[0][0], EMBED, EMBED,
                     gm * 128, (r & 3) * 128,
                     g_Q16, EMBED, nullptr, nullptr, nullptr, 1.0f, nullptr, 0, dynsm);
        signal(8 + gm);                               // qcnt target 4
    } else if (id < OFF_Z){
        // ---- gemmE ----
        const int e = id - OFF_E;
        const int b = e >> 9, r = e & 511, by = r >> 5, bx = r & 31;
        gate(1, PB);                                  // y16 ready
        gate(8 + b * 16 + by, 4);                     // Q' rows
        gemm_core<3>(g_Q16 + (size_t)b * QLEN * EMBED, EMBED,
                     g_y16 + (size_t)b * KLEN * EMBED, EMBED, EMBED,
                     by * 128, bx * 128,
                     g_E16 + (size_t)b * QLEN * KLEN, KLEN,
                     nullptr, nullptr, nullptr, scale,
                     g_Esum + (size_t)b * QLEN * NBLK, bx, dynsm);
        signal(136 + b * 16 + by);                    // ecnt target 32
    } else if (id < OFF_O){
        // ---- gemmZ (Z reuses Q16) ----
        const int z = id - OFF_Z;
        const int b = z >> 6, r = z & 63, my = r >> 2, nx = r & 3;
        gate(136 + b * 16 + my, 32);
        gemm_core<4>(g_E16 + (size_t)b * QLEN * KLEN, KLEN,
                     g_yT16 + (size_t)b * EMBED * KLEN, KLEN, KLEN,
                     my * 128, nx * 128,
                     g_Q16 + (size_t)b * QLEN * EMBED, EMBED,
                     nullptr, nullptr, nullptr, 1.0f,
                     g_Esum + (size_t)b * QLEN * NBLK, 0, dynsm);
        signal(264 + b * 16 + my);                    // zcnt target 4
    } else {
        // ---- gemmOut: out = x + Z @ Wvo^T + bo ----
        const int o = id - OFF_O;
        const int gm = o >> 2;
        gate(264 + gm, 4);
        gemm_core<2>(g_Q16, EMBED, &g_W16[2][0], EMBED, EMBED,
                     gm * 128, (o & 3) * 128,
                     nullptr, EMBED, out, x, bo, 1.0f, nullptr, 0, dynsm);
    }
}

// ---------------- launch ----------------
extern "C" void kernel_launch(void* const* d_in, const int* in_sizes, int n_in,
                              void* d_out, int out_size)
{
    const float* x  = (const float*)d_in[0];
    const float* y  = (const float*)d_in[1];
    const float* Wq = (const float*)d_in[2];
    const float* Wk = (const float*)d_in[3];
    const float* Wv = (const float*)d_in[4];
    const float* Wo = (const float*)d_in[5];
    const float* bo = (const float*)d_in[6];
    float* out = (float*)d_out;

    int* cnt;
    cudaGetSymbolAddress((void**)&cnt, g_cnt);
    cudaFuncSetAttribute(mega, cudaFuncAttributeMaxDynamicSharedMemorySize, GSMEM);

    const float sc = 1.0f / sqrtf((float)EMBED);

    cudaMemsetAsync(cnt, 0, 512 * sizeof(int));
    mega<<<NTOT, 256, GSMEM>>>(x, y, Wq, Wk, Wv, Wo, bo, out, sc);
}